// round 10
// baseline (speedup 1.0000x reference)
#include <cuda_runtime.h>

#define KV 16
#define DIM 15
#define NPIX (2048 * 2048)
#define TPB 256
// one thread = two pixel-quads; each quad = two packed f32x2 pairs per plane (LDG.128)

typedef unsigned long long u64;

__device__ __forceinline__ u64 ffma2(u64 a, u64 b, u64 c) {
    u64 d;
    asm("fma.rn.f32x2 %0, %1, %2, %3;" : "=l"(d) : "l"(a), "l"(b), "l"(c));
    return d;
}
__device__ __forceinline__ u64 fadd2(u64 a, u64 b) {
    u64 d;
    asm("add.rn.f32x2 %0, %1, %2;" : "=l"(d) : "l"(a), "l"(b));
    return d;
}
__device__ __forceinline__ u64 pack2(float x, float y) {
    u64 p;
    asm("mov.b64 %0, {%1, %2};" : "=l"(p) : "f"(x), "f"(y));
    return p;
}
__device__ __forceinline__ void unpack2(u64 p, float& x, float& y) {
    asm("mov.b64 {%0, %1}, %2;" : "=f"(x), "=f"(y) : "l"(p));
}
__device__ __forceinline__ void prefetch_l2(const void* p) {
    asm volatile("prefetch.global.L2 [%0];" :: "l"(p));
}

// Embed vertex index k into the low 4 mantissa bits of t (one LOP3), so the
// argmin collapses to a chain of FMNMX. Perturbation <= 16 ulp.
__device__ __forceinline__ float embed_idx(float t, int k) {
    unsigned r;
    asm("lop3.b32 %0, %1, 0xFFFFFFF0, %2, 0xEA;"  // (a & b) | c
        : "=r"(r) : "r"(__float_as_uint(t)), "r"(k));
    return __uint_as_float(r);
}

// Weight layout, per vertex k: 8 ulonglong2.
//   [k][m].x / .y = packed (-2*v[k][2m], dup) / (-2*v[k][2m+1], dup)  for m<7
//   [k][7].x      = packed pair for j=14
//   [k][7].y      = packed (||v_k||^2, ||v_k||^2)
__constant__ ulonglong2 c_wp[KV][8];

// prep writes through the global alias of c_wp; const cache refills per launch.
__global__ void prep_kernel(const float* __restrict__ v, ulonglong2* __restrict__ wp) {
    const int t = threadIdx.x;
    if (t < KV) {
        float b = 0.0f;
        #pragma unroll
        for (int j = 0; j < DIM; ++j) {
            float a = v[t * DIM + j];
            b = fmaf(a, a, b);
        }
        #pragma unroll
        for (int m = 0; m < 7; ++m) {
            float w0 = -2.0f * v[t * DIM + 2 * m];
            float w1 = -2.0f * v[t * DIM + 2 * m + 1];
            wp[t * 8 + m] = make_ulonglong2(pack2(w0, w0), pack2(w1, w1));
        }
        float w14 = -2.0f * v[t * DIM + 14];
        wp[t * 8 + 7] = make_ulonglong2(pack2(w14, w14), pack2(b, b));
    }
}

// t_k = ||v_k||^2 - 2 v_k . z ; dmin = sqrt(max(zz + t_min, 0))
__device__ __forceinline__ void compute_store(const u64* zlo, const u64* zhi,
                                              float* __restrict__ out, size_t p) {
    float b0 = __int_as_float(0x7f7fffff), b1 = b0, b2 = b0, b3 = b0;  // FLT_MAX

    #pragma unroll
    for (int k = 0; k < KV; ++k) {
        ulonglong2 w7 = c_wp[k][7];
        u64 la = w7.y, ha = w7.y;         // ||v_k||^2 pair
        u64 lb = 0ull, hb = 0ull;
        la = ffma2(w7.x, zlo[14], la);
        ha = ffma2(w7.x, zhi[14], ha);
        #pragma unroll
        for (int m = 0; m < 7; ++m) {
            ulonglong2 w = c_wp[k][m];
            la = ffma2(w.x, zlo[2 * m], la);
            ha = ffma2(w.x, zhi[2 * m], ha);
            lb = ffma2(w.y, zlo[2 * m + 1], lb);
            hb = ffma2(w.y, zhi[2 * m + 1], hb);
        }
        u64 tlo = fadd2(la, lb);
        u64 thi = fadd2(ha, hb);

        float t0, t1, t2, t3;
        unpack2(tlo, t0, t1);
        unpack2(thi, t2, t3);
        b0 = fminf(b0, embed_idx(t0, k));
        b1 = fminf(b1, embed_idx(t1, k));
        b2 = fminf(b2, embed_idx(t2, k));
        b3 = fminf(b3, embed_idx(t3, k));
    }

    u64 zza_lo = 0ull, zzb_lo = 0ull, zza_hi = 0ull, zzb_hi = 0ull;
    #pragma unroll
    for (int j = 0; j < DIM; j += 2) {
        zza_lo = ffma2(zlo[j], zlo[j], zza_lo);
        zza_hi = ffma2(zhi[j], zhi[j], zza_hi);
        if (j + 1 < DIM) {
            zzb_lo = ffma2(zlo[j + 1], zlo[j + 1], zzb_lo);
            zzb_hi = ffma2(zhi[j + 1], zhi[j + 1], zzb_hi);
        }
    }
    float zz0, zz1, zz2, zz3;
    unpack2(fadd2(zza_lo, zzb_lo), zz0, zz1);
    unpack2(fadd2(zza_hi, zzb_hi), zz2, zz3);

    unsigned u0 = __float_as_uint(b0), u1 = __float_as_uint(b1);
    unsigned u2 = __float_as_uint(b2), u3 = __float_as_uint(b3);
    float4 xo = make_float4((float)(u0 & 15u), (float)(u1 & 15u),
                            (float)(u2 & 15u), (float)(u3 & 15u));
    float m0 = __uint_as_float(u0 & 0xFFFFFFF0u);
    float m1 = __uint_as_float(u1 & 0xFFFFFFF0u);
    float m2 = __uint_as_float(u2 & 0xFFFFFFF0u);
    float m3 = __uint_as_float(u3 & 0xFFFFFFF0u);
    float4 dm = make_float4(sqrtf(fmaxf(zz0 + m0, 0.0f)),
                            sqrtf(fmaxf(zz1 + m1, 0.0f)),
                            sqrtf(fmaxf(zz2 + m2, 0.0f)),
                            sqrtf(fmaxf(zz3 + m3, 0.0f)));

    __stcs((float4*)(out + 4 * p), xo);
    __stcs((float4*)(out + (size_t)NPIX + 4 * p), dm);
}

#define NQUAD (NPIX / 4)          // total pixel-quads
#define QSTRIDE (NQUAD / 2)       // second quad offset per thread

__global__ __launch_bounds__(TPB, 3) void gum_kernel(const float* __restrict__ z,
                                                     float* __restrict__ out) {
    const int t = threadIdx.x;
    const size_t p1 = (size_t)blockIdx.x * TPB + t;
    const size_t p2 = p1 + QSTRIDE;
    const u64* zp = (const u64*)z;

    // Quad 1: front-batch 15 LDG.128
    u64 zlo[DIM], zhi[DIM];
    #pragma unroll
    for (int j = 0; j < DIM; ++j) {
        ulonglong2 zv = __ldcs((const ulonglong2*)(zp + (size_t)j * (NPIX / 2) + 2 * p1));
        zlo[j] = zv.x;
        zhi[j] = zv.y;
    }

    // L2-prefetch quad 2's lines (one lane per 128B line; no dest registers).
    // These stream from DRAM under quad 1's compute shadow.
    if ((t & 7) == 0) {
        #pragma unroll
        for (int j = 0; j < DIM; ++j)
            prefetch_l2(zp + (size_t)j * (NPIX / 2) + 2 * p2);
    }

    compute_store(zlo, zhi, out, p1);

    // Quad 2: loads now mostly hit L2
    #pragma unroll
    for (int j = 0; j < DIM; ++j) {
        ulonglong2 zv = __ldcs((const ulonglong2*)(zp + (size_t)j * (NPIX / 2) + 2 * p2));
        zlo[j] = zv.x;
        zhi[j] = zv.y;
    }

    compute_store(zlo, zhi, out, p2);
}

extern "C" void kernel_launch(void* const* d_in, const int* in_sizes, int n_in,
                              void* d_out, int out_size) {
    const float* z = (const float*)d_in[0];  // (15, 2048, 2048) fp32
    const float* v = (const float*)d_in[1];  // (16, 15) fp32
    float* out = (float*)d_out;              // [X (as float) | dmin], each NPIX

    void* wp = nullptr;
    cudaGetSymbolAddress(&wp, c_wp);         // global alias of constant bank
    prep_kernel<<<1, 32>>>(v, (ulonglong2*)wp);

    const int nblocks = NQUAD / (TPB * 2);   // 2048
    gum_kernel<<<nblocks, TPB>>>(z, out);
}

// round 11
// speedup vs baseline: 1.0366x; 1.0366x over previous
#include <cuda_runtime.h>

#define KV 16
#define DIM 15
#define NPIX (2048 * 2048)
#define TPB 256
// one thread = 4 pixels, as two packed f32x2 pairs per plane (LDG.128)

typedef unsigned long long u64;

__device__ __forceinline__ u64 ffma2(u64 a, u64 b, u64 c) {
    u64 d;
    asm("fma.rn.f32x2 %0, %1, %2, %3;" : "=l"(d) : "l"(a), "l"(b), "l"(c));
    return d;
}
__device__ __forceinline__ u64 fadd2(u64 a, u64 b) {
    u64 d;
    asm("add.rn.f32x2 %0, %1, %2;" : "=l"(d) : "l"(a), "l"(b));
    return d;
}
__device__ __forceinline__ u64 pack2(float x, float y) {
    u64 p;
    asm("mov.b64 %0, {%1, %2};" : "=l"(p) : "f"(x), "f"(y));
    return p;
}
__device__ __forceinline__ void unpack2(u64 p, float& x, float& y) {
    asm("mov.b64 {%0, %1}, %2;" : "=f"(x), "=f"(y) : "l"(p));
}

// Embed vertex index k into the low 4 mantissa bits of t (one LOP3), so the
// argmin collapses to a chain of FMNMX. Perturbation <= 16 ulp.
__device__ __forceinline__ float embed_idx(float t, int k) {
    unsigned r;
    asm("lop3.b32 %0, %1, 0xFFFFFFF0, %2, 0xEA;"  // (a & b) | c
        : "=r"(r) : "r"(__float_as_uint(t)), "r"(k));
    return __uint_as_float(r);
}

// Weight layout, per vertex k: 8 ulonglong2.
//   [k][m].x / .y = packed (-2*v[k][2m], dup) / (-2*v[k][2m+1], dup)  for m<7
//   [k][7].x      = packed pair for j=14
//   [k][7].y      = packed (||v_k||^2, ||v_k||^2)
__constant__ ulonglong2 c_wp[KV][8];

// prep writes through the global alias of c_wp; const cache refills per launch.
__global__ void prep_kernel(const float* __restrict__ v, ulonglong2* __restrict__ wp) {
    const int t = threadIdx.x;
    if (t < KV) {
        float b = 0.0f;
        #pragma unroll
        for (int j = 0; j < DIM; ++j) {
            float a = v[t * DIM + j];
            b = fmaf(a, a, b);
        }
        #pragma unroll
        for (int m = 0; m < 7; ++m) {
            float w0 = -2.0f * v[t * DIM + 2 * m];
            float w1 = -2.0f * v[t * DIM + 2 * m + 1];
            wp[t * 8 + m] = make_ulonglong2(pack2(w0, w0), pack2(w1, w1));
        }
        float w14 = -2.0f * v[t * DIM + 14];
        wp[t * 8 + 7] = make_ulonglong2(pack2(w14, w14), pack2(b, b));
    }
}

// t_k = ||v_k||^2 - 2 v_k . z   (monotone in distance; argmin matches)
// dmin = sqrt(max(zz + t_min, 0))

__global__ __launch_bounds__(TPB, 3) void gum_kernel(const float* __restrict__ z,
                                                     float* __restrict__ out) {
    const int t = threadIdx.x;
    const size_t p = (size_t)blockIdx.x * TPB + t;  // pixel-quad index
    const u64* zp = (const u64*)z;

    // Front-batch all 15 global loads as LDG.128 (1920 B in flight per warp)
    u64 zlo[DIM], zhi[DIM];
    #pragma unroll
    for (int j = 0; j < DIM; ++j) {
        ulonglong2 zv = __ldcs((const ulonglong2*)(zp + (size_t)j * (NPIX / 2) + 2 * p));
        zlo[j] = zv.x;  // pixels (4p, 4p+1)
        zhi[j] = zv.y;  // pixels (4p+2, 4p+3)
    }

    float b0 = __int_as_float(0x7f7fffff), b1 = b0, b2 = b0, b3 = b0;  // FLT_MAX

    #pragma unroll
    for (int k = 0; k < KV; ++k) {
        // weights from constant bank (uniform port) — literal indices.
        // j=14 (the LAST load issued) is folded in LAST, so the first FFMAs
        // of each k depend only on the earliest loads — compute overlaps the
        // tail of the load burst instead of waiting for all 15 returns.
        ulonglong2 w7 = c_wp[k][7];
        u64 la = w7.y, ha = w7.y;         // ||v_k||^2 pair
        u64 lb = 0ull, hb = 0ull;
        #pragma unroll
        for (int m = 0; m < 7; ++m) {
            ulonglong2 w = c_wp[k][m];
            la = ffma2(w.x, zlo[2 * m], la);
            ha = ffma2(w.x, zhi[2 * m], ha);
            lb = ffma2(w.y, zlo[2 * m + 1], lb);
            hb = ffma2(w.y, zhi[2 * m + 1], hb);
        }
        la = ffma2(w7.x, zlo[14], la);
        ha = ffma2(w7.x, zhi[14], ha);
        u64 tlo = fadd2(la, lb);
        u64 thi = fadd2(ha, hb);

        float t0, t1, t2, t3;
        unpack2(tlo, t0, t1);
        unpack2(thi, t2, t3);
        // branchless argmin: LOP3 (embed k) + FMNMX per pixel
        b0 = fminf(b0, embed_idx(t0, k));
        b1 = fminf(b1, embed_idx(t1, k));
        b2 = fminf(b2, embed_idx(t2, k));
        b3 = fminf(b3, embed_idx(t3, k));
    }

    // ||z||^2 (zlo/zhi stay live through the k-loop anyway)
    u64 zza_lo = 0ull, zzb_lo = 0ull, zza_hi = 0ull, zzb_hi = 0ull;
    #pragma unroll
    for (int j = 0; j < DIM; j += 2) {
        zza_lo = ffma2(zlo[j], zlo[j], zza_lo);
        zza_hi = ffma2(zhi[j], zhi[j], zza_hi);
        if (j + 1 < DIM) {
            zzb_lo = ffma2(zlo[j + 1], zlo[j + 1], zzb_lo);
            zzb_hi = ffma2(zhi[j + 1], zhi[j + 1], zzb_hi);
        }
    }
    float zz0, zz1, zz2, zz3;
    unpack2(fadd2(zza_lo, zzb_lo), zz0, zz1);
    unpack2(fadd2(zza_hi, zzb_hi), zz2, zz3);

    // winner index = low 4 bits; masked value = t_min (16 ulp perturbation)
    unsigned u0 = __float_as_uint(b0), u1 = __float_as_uint(b1);
    unsigned u2 = __float_as_uint(b2), u3 = __float_as_uint(b3);
    float4 xo = make_float4((float)(u0 & 15u), (float)(u1 & 15u),
                            (float)(u2 & 15u), (float)(u3 & 15u));
    float m0 = __uint_as_float(u0 & 0xFFFFFFF0u);
    float m1 = __uint_as_float(u1 & 0xFFFFFFF0u);
    float m2 = __uint_as_float(u2 & 0xFFFFFFF0u);
    float m3 = __uint_as_float(u3 & 0xFFFFFFF0u);
    float4 dm = make_float4(sqrtf(fmaxf(zz0 + m0, 0.0f)),
                            sqrtf(fmaxf(zz1 + m1, 0.0f)),
                            sqrtf(fmaxf(zz2 + m2, 0.0f)),
                            sqrtf(fmaxf(zz3 + m3, 0.0f)));

    __stcs((float4*)(out + 4 * p), xo);
    __stcs((float4*)(out + (size_t)NPIX + 4 * p), dm);
}

extern "C" void kernel_launch(void* const* d_in, const int* in_sizes, int n_in,
                              void* d_out, int out_size) {
    const float* z = (const float*)d_in[0];  // (15, 2048, 2048) fp32
    const float* v = (const float*)d_in[1];  // (16, 15) fp32
    float* out = (float*)d_out;              // [X (as float) | dmin], each NPIX

    void* wp = nullptr;
    cudaGetSymbolAddress(&wp, c_wp);         // global alias of constant bank
    prep_kernel<<<1, 32>>>(v, (ulonglong2*)wp);

    const int nblocks = NPIX / (TPB * 4);    // 4096
    gum_kernel<<<nblocks, TPB>>>(z, out);
}

// round 12
// speedup vs baseline: 1.0426x; 1.0058x over previous
#include <cuda_runtime.h>

#define KV 16
#define DIM 15
#define NPIX (2048 * 2048)
#define TPB 256
// one thread = 4 pixels, as two packed f32x2 pairs per plane (LDG.128)

typedef unsigned long long u64;

__device__ __forceinline__ u64 ffma2(u64 a, u64 b, u64 c) {
    u64 d;
    asm("fma.rn.f32x2 %0, %1, %2, %3;" : "=l"(d) : "l"(a), "l"(b), "l"(c));
    return d;
}
__device__ __forceinline__ u64 fadd2(u64 a, u64 b) {
    u64 d;
    asm("add.rn.f32x2 %0, %1, %2;" : "=l"(d) : "l"(a), "l"(b));
    return d;
}
__device__ __forceinline__ u64 pack2(float x, float y) {
    u64 p;
    asm("mov.b64 %0, {%1, %2};" : "=l"(p) : "f"(x), "f"(y));
    return p;
}
__device__ __forceinline__ void unpack2(u64 p, float& x, float& y) {
    asm("mov.b64 {%0, %1}, %2;" : "=f"(x), "=f"(y) : "l"(p));
}

// Embed vertex index k into the low 4 mantissa bits of t (one LOP3), so the
// argmin collapses to a chain of FMNMX. Perturbation <= 16 ulp.
__device__ __forceinline__ float embed_idx(float t, int k) {
    unsigned r;
    asm("lop3.b32 %0, %1, 0xFFFFFFF0, %2, 0xEA;"  // (a & b) | c
        : "=r"(r) : "r"(__float_as_uint(t)), "r"(k));
    return __uint_as_float(r);
}

// Weight layout, per vertex k: 8 ulonglong2.
//   [k][m].x / .y = packed (-2*v[k][2m], dup) / (-2*v[k][2m+1], dup)  for m<7
//   [k][7].x      = packed pair for j=14
//   [k][7].y      = packed (||v_k||^2, ||v_k||^2)
__constant__ ulonglong2 c_wp[KV][8];

// prep writes through the global alias of c_wp; const cache refills per launch.
__global__ void prep_kernel(const float* __restrict__ v, ulonglong2* __restrict__ wp) {
    const int t = threadIdx.x;
    if (t < KV) {
        float b = 0.0f;
        #pragma unroll
        for (int j = 0; j < DIM; ++j) {
            float a = v[t * DIM + j];
            b = fmaf(a, a, b);
        }
        #pragma unroll
        for (int m = 0; m < 7; ++m) {
            float w0 = -2.0f * v[t * DIM + 2 * m];
            float w1 = -2.0f * v[t * DIM + 2 * m + 1];
            wp[t * 8 + m] = make_ulonglong2(pack2(w0, w0), pack2(w1, w1));
        }
        float w14 = -2.0f * v[t * DIM + 14];
        wp[t * 8 + 7] = make_ulonglong2(pack2(w14, w14), pack2(b, b));
    }
}

// t_k = ||v_k||^2 - 2 v_k . z   (monotone in distance; argmin matches)
// dmin = sqrt(max(zz + t_min, 0))

__global__ __launch_bounds__(TPB, 3) void gum_kernel(const float* __restrict__ z,
                                                     float* __restrict__ out) {
    const int t = threadIdx.x;
    const size_t p = (size_t)blockIdx.x * TPB + t;  // pixel-quad index
    const u64* zp = (const u64*)z;

    // Front-batch all 15 global loads as LDG.128 (1920 B in flight per warp)
    u64 zlo[DIM], zhi[DIM];
    #pragma unroll
    for (int j = 0; j < DIM; ++j) {
        ulonglong2 zv = __ldcs((const ulonglong2*)(zp + (size_t)j * (NPIX / 2) + 2 * p));
        zlo[j] = zv.x;  // pixels (4p, 4p+1)
        zhi[j] = zv.y;  // pixels (4p+2, 4p+3)
    }

    float b0 = __int_as_float(0x7f7fffff), b1 = b0, b2 = b0, b3 = b0;  // FLT_MAX

    #pragma unroll
    for (int k = 0; k < KV; ++k) {
        // Single accumulator chain per pixel-pair: the fully-unrolled k-loop
        // already provides 32 independent chains of ILP; intra-k splitting
        // only cost extra FADD2/zero-init issue slots.
        ulonglong2 w7 = c_wp[k][7];
        u64 la = w7.y, ha = w7.y;         // ||v_k||^2 pair
        #pragma unroll
        for (int m = 0; m < 7; ++m) {
            ulonglong2 w = c_wp[k][m];
            la = ffma2(w.x, zlo[2 * m], la);
            ha = ffma2(w.x, zhi[2 * m], ha);
            la = ffma2(w.y, zlo[2 * m + 1], la);
            ha = ffma2(w.y, zhi[2 * m + 1], ha);
        }
        la = ffma2(w7.x, zlo[14], la);    // last-issued load folded last
        ha = ffma2(w7.x, zhi[14], ha);

        float t0, t1, t2, t3;
        unpack2(la, t0, t1);
        unpack2(ha, t2, t3);
        // branchless argmin: LOP3 (embed k) + FMNMX per pixel
        b0 = fminf(b0, embed_idx(t0, k));
        b1 = fminf(b1, embed_idx(t1, k));
        b2 = fminf(b2, embed_idx(t2, k));
        b3 = fminf(b3, embed_idx(t3, k));
    }

    // ||z||^2 (zlo/zhi stay live through the k-loop anyway)
    u64 zza_lo = 0ull, zzb_lo = 0ull, zza_hi = 0ull, zzb_hi = 0ull;
    #pragma unroll
    for (int j = 0; j < DIM; j += 2) {
        zza_lo = ffma2(zlo[j], zlo[j], zza_lo);
        zza_hi = ffma2(zhi[j], zhi[j], zza_hi);
        if (j + 1 < DIM) {
            zzb_lo = ffma2(zlo[j + 1], zlo[j + 1], zzb_lo);
            zzb_hi = ffma2(zhi[j + 1], zhi[j + 1], zzb_hi);
        }
    }
    float zz0, zz1, zz2, zz3;
    unpack2(fadd2(zza_lo, zzb_lo), zz0, zz1);
    unpack2(fadd2(zza_hi, zzb_hi), zz2, zz3);

    // winner index = low 4 bits; masked value = t_min (16 ulp perturbation)
    unsigned u0 = __float_as_uint(b0), u1 = __float_as_uint(b1);
    unsigned u2 = __float_as_uint(b2), u3 = __float_as_uint(b3);
    float4 xo = make_float4((float)(u0 & 15u), (float)(u1 & 15u),
                            (float)(u2 & 15u), (float)(u3 & 15u));
    float m0 = __uint_as_float(u0 & 0xFFFFFFF0u);
    float m1 = __uint_as_float(u1 & 0xFFFFFFF0u);
    float m2 = __uint_as_float(u2 & 0xFFFFFFF0u);
    float m3 = __uint_as_float(u3 & 0xFFFFFFF0u);
    float4 dm = make_float4(sqrtf(fmaxf(zz0 + m0, 0.0f)),
                            sqrtf(fmaxf(zz1 + m1, 0.0f)),
                            sqrtf(fmaxf(zz2 + m2, 0.0f)),
                            sqrtf(fmaxf(zz3 + m3, 0.0f)));

    __stcs((float4*)(out + 4 * p), xo);
    __stcs((float4*)(out + (size_t)NPIX + 4 * p), dm);
}

extern "C" void kernel_launch(void* const* d_in, const int* in_sizes, int n_in,
                              void* d_out, int out_size) {
    const float* z = (const float*)d_in[0];  // (15, 2048, 2048) fp32
    const float* v = (const float*)d_in[1];  // (16, 15) fp32
    float* out = (float*)d_out;              // [X (as float) | dmin], each NPIX

    void* wp = nullptr;
    cudaGetSymbolAddress(&wp, c_wp);         // global alias of constant bank
    prep_kernel<<<1, 32>>>(v, (ulonglong2*)wp);

    const int nblocks = NPIX / (TPB * 4);    // 4096
    gum_kernel<<<nblocks, TPB>>>(z, out);
}